// round 8
// baseline (speedup 1.0000x reference)
#include <cuda_runtime.h>
#include <math_constants.h>
#include <cstdint>

#define BB   512
#define NN   600
#define HH   256
#define HHF  128          // h per CTA (half)
#define KK   9
#define WIN  129
#define PAD  4
#define PWIN 137
#define NP   (NN + 2*PAD)   // 608
#define NQC  (2*KK + 1)
#define TPB  256

// output offsets (floats)
#define O_CTX  0
#define O_UNP  (BB*HH)                 // 131072
#define O_FULL (O_UNP + BB*NN)         // 438272
#define O_OUT4 (O_FULL + BB*NP)        // 749568
#define O_NS   (O_OUT4 + BB*NP)        // 1060864

#define SPITCH 144

__device__ __forceinline__ unsigned int smem_u32(const void* p) {
    return (unsigned int)__cvta_generic_to_shared(p);
}
__device__ __forceinline__ float peer_ld_f32(unsigned int local_addr, unsigned int peer_rank) {
    unsigned int pa;
    asm("mapa.shared::cluster.u32 %0, %1, %2;" : "=r"(pa) : "r"(local_addr), "r"(peer_rank));
    float v;
    asm volatile("ld.shared::cluster.f32 %0, [%1];" : "=f"(v) : "r"(pa));
    return v;
}

__global__ __launch_bounds__(TPB, 8) __cluster_dims__(2, 1, 1)
void attn_cluster_kernel(
    const float* __restrict__ tokens,        // (B, N, H)
    const float* __restrict__ token_keys,    // (B, H, N)
    const int*   __restrict__ num_tokens,    // (B,)
    const float* __restrict__ query,         // (B, H)
    const float* __restrict__ alignment,     // (B, NP)
    const float* __restrict__ cum_alignment, // (B, NP)
    const int*   __restrict__ window_start,  // (B,)
    const float* __restrict__ conv_w,        // (H, 2, K)
    const float* __restrict__ conv_b,        // (H,)
    float* __restrict__ out)
{
    const int rank = blockIdx.x & 1;
    const int b    = blockIdx.x >> 1;
    const int t    = threadIdx.x;
    const int lane = t & 31;
    const int warp = t >> 5;          // 0..7

    __shared__ alignas(16) float part_s[8][SPITCH];  // per-warp score partials (p-space)
    __shared__ alignas(16) float exch_s[SPITCH];     // this CTA's h-half partial (p-space)
    __shared__ alignas(16) float ctx_s[8][HHF];      // context row-group partials
    __shared__ float q_s[HH];
    __shared__ float pos_s[2][PWIN];
    __shared__ float qc_s[NQC];
    __shared__ float sc_s[WIN];
    __shared__ float al_s[WIN];
    __shared__ float red_s[8][NQC];
    __shared__ float rval_s[8];
    __shared__ int   ridx_s[8];
    __shared__ int   argmax_sh;

    const int ws = window_start[b];
    const int nt = num_tokens[b];
    const int a  = ws & 3;

    // ---- prefetch this CTA's token half-rows into L2 (half-row = 512B, row
    //      stride 1KB) so the context stream overlaps the score stream.
    {
        const char* tb = (const char*)(tokens + (size_t)b*NN*HH + (size_t)ws*HH + rank*HHF);
        #pragma unroll 4
        for (int i = t; i < WIN*4; i += TPB)    // 129 rows x 4 sectors of 128B
            asm volatile("prefetch.global.L2 [%0];" :: "l"(tb + (size_t)(i>>2)*1024 + (i&3)*128));
    }

    // ---- full query + conv fold (all 256 threads, h = t)
    {
        const float qv = query[b*HH + t];
        q_s[t] = qv;
        const float* cw = conv_w + t * (2*KK);
        float vals[NQC];
        #pragma unroll
        for (int j = 0; j < 2*KK; j++) vals[j] = qv * cw[j];
        vals[2*KK] = qv * conv_b[t];
        #pragma unroll
        for (int j = 0; j < NQC; j++) {
            float v = vals[j];
            #pragma unroll
            for (int off = 16; off; off >>= 1)
                v += __shfl_down_sync(0xffffffffu, v, off);
            if (lane == 0) red_s[warp][j] = v;
        }
    }
    __syncthreads();

    // ---- position features + qc combine
    if (t < PWIN) {
        const int g = b*NP + ws + t;
        pos_s[0][t] = cum_alignment[g] * (1.0f/1.5f) - 1.0f;
        pos_s[1][t] = alignment[g]     * 2.0f        - 1.0f;
    }
    if (t >= 224 && t - 224 < NQC) {
        const int j = t - 224;
        float s = 0.f;
        #pragma unroll
        for (int wpi = 0; wpi < 8; wpi++) s += red_s[wpi][j];
        qc_s[j] = s;
    }

    // ---- score matvec over this CTA's h-half, float4 loads.
    //      lane l covers p = 4l..4l+3 (rel ws-a); lane 0 also p=128..131.
    {
        float4 acc  = make_float4(0.f, 0.f, 0.f, 0.f);
        float4 acce = make_float4(0.f, 0.f, 0.f, 0.f);
        const float* kp = token_keys + (size_t)b*HH*NN + (size_t)(rank*HHF)*NN + (ws - a);
        #pragma unroll 4
        for (int h = warp; h < HHF; h += 8) {
            const float qh = q_s[rank*HHF + h];
            const float4* row = (const float4*)(kp + (size_t)h*NN);
            const float4 v4 = __ldg(row + lane);
            acc.x += qh * v4.x;  acc.y += qh * v4.y;
            acc.z += qh * v4.z;  acc.w += qh * v4.w;
            if (lane == 0) {
                const float4 e4 = __ldg(row + 32);
                acce.x += qh * e4.x;  acce.y += qh * e4.y;
                acce.z += qh * e4.z;  acce.w += qh * e4.w;
            }
        }
        *(float4*)&part_s[warp][4*lane] = acc;
        if (lane == 0) *(float4*)&part_s[warp][128] = acce;
    }
    __syncthreads();

    // ---- reduce 8 warps -> this CTA's half-partial in p-space
    if (t < 132) {
        float s = 0.f;
        #pragma unroll
        for (int i = 0; i < 8; i++) s += part_s[i][t];
        exch_s[t] = s;
    }

    // ---- exchange halves across the cluster
    asm volatile("barrier.cluster.arrive.aligned;" ::: "memory");
    asm volatile("barrier.cluster.wait.aligned;"   ::: "memory");

    if (t < WIN) {
        const float own  = exch_s[t + a];
        const float peer = peer_ld_f32(smem_u32(&exch_s[t + a]), (unsigned)(rank ^ 1));

        float cacc = qc_s[2*KK];
        #pragma unroll
        for (int k = 0; k < KK; k++)
            cacc += pos_s[0][t+k] * qc_s[k] + pos_s[1][t+k] * qc_s[KK+k];

        const float s = (own + peer + cacc) * (1.0f/16.0f);
        sc_s[t] = ((ws + t) < nt) ? s : -CUDART_INF_F;
    }

    // second cluster barrier: both CTAs finished reading peer SMEM
    asm volatile("barrier.cluster.arrive.aligned;" ::: "memory");
    asm volatile("barrier.cluster.wait.aligned;"   ::: "memory");

    // ---- softmax over WIN
    float v = (t < WIN) ? sc_s[t] : -CUDART_INF_F;
    #pragma unroll
    for (int off = 16; off; off >>= 1)
        v = fmaxf(v, __shfl_down_sync(0xffffffffu, v, off));
    if (lane == 0) rval_s[warp] = v;
    __syncthreads();
    if (t == 0) {
        float m = rval_s[0];
        #pragma unroll
        for (int i = 1; i < 8; i++) m = fmaxf(m, rval_s[i]);
        rval_s[0] = m;
    }
    __syncthreads();
    const float smax = rval_s[0];
    __syncthreads();

    const float e = (t < WIN) ? expf(sc_s[t] - smax) : 0.f;
    float sv = e;
    #pragma unroll
    for (int off = 16; off; off >>= 1)
        sv += __shfl_down_sync(0xffffffffu, sv, off);
    if (lane == 0) rval_s[warp] = sv;
    __syncthreads();
    if (t == 0) {
        float s = 0.f;
        #pragma unroll
        for (int i = 0; i < 8; i++) s += rval_s[i];
        rval_s[0] = s;
    }
    __syncthreads();
    const float inv = 1.0f / rval_s[0];
    const float al  = e * inv;
    if (t < WIN) al_s[t] = al;
    __syncthreads();

    // ---- argmax (ties -> first, JAX semantics), only rank 0 needs it
    if (rank == 0) {
        float av = (t < WIN) ? al : -1.f;
        int   ai = t;
        #pragma unroll
        for (int off = 16; off; off >>= 1) {
            float v2 = __shfl_down_sync(0xffffffffu, av, off);
            int   i2 = __shfl_down_sync(0xffffffffu, ai, off);
            if (v2 > av || (v2 == av && i2 < ai)) { av = v2; ai = i2; }
        }
        if (lane == 0) { rval_s[warp] = av; ridx_s[warp] = ai; }
        __syncthreads();
        if (t == 0) {
            float bv = rval_s[0]; int bi = ridx_s[0];
            #pragma unroll
            for (int i = 1; i < 8; i++) {
                if (rval_s[i] > bv || (rval_s[i] == bv && ridx_s[i] < bi)) {
                    bv = rval_s[i]; bi = ridx_s[i];
                }
            }
            argmax_sh = bi;
        }
    }

    // ---- context over this CTA's h-half with float4.
    //      hv = t&31 (float4 within the 512B half-row), rg = t>>5 (0..7).
    {
        const int hv = t & 31;
        const int rg = t >> 5;
        const float4* tp = (const float4*)(tokens + (size_t)b*NN*HH + (size_t)ws*HH + rank*HHF) + hv;
        float4 acc = make_float4(0.f, 0.f, 0.f, 0.f);
        #pragma unroll 4
        for (int w = rg; w < WIN; w += 8) {
            const float aw = al_s[w];
            const float4 v4 = __ldg(tp + (size_t)w * (HH/4));
            acc.x += aw * v4.x;  acc.y += aw * v4.y;
            acc.z += aw * v4.z;  acc.w += aw * v4.w;
        }
        *(float4*)&ctx_s[rg][4*hv] = acc;
    }
    __syncthreads();
    if (t < HHF) {
        float s = 0.f;
        #pragma unroll
        for (int g = 0; g < 8; g++) s += ctx_s[g][t];
        out[O_CTX + b*HH + rank*HHF + t] = s;
    }

    // ---- full_align / unpadded / cum+full, split by rank: j in [rank*304, +304)
    {
        const float* cum = cum_alignment + (size_t)b*NP;
        const int jbeg = rank * 304;
        const int jend = jbeg + 304;
        for (int j = jbeg + t; j < jend; j += TPB) {
            const int wrel = j - PAD - ws;
            const float fa = (wrel >= 0 && wrel < WIN) ? al_s[wrel] : 0.f;
            out[O_FULL + (size_t)b*NP + j] = fa;
            out[O_OUT4 + (size_t)b*NP + j] = cum[j] + fa;
            if (j >= PAD && j < NP - PAD)
                out[O_UNP + (size_t)b*NN + (j - PAD)] = fa;
        }
    }

    // ---- new window start
    if (rank == 0 && t == 0) {
        const int g  = ws + argmax_sh + PAD;
        int ns = g - PWIN/2;
        ns = max(ws, ns);
        ns = min(ns, nt - WIN);
        ns = max(ns, 0);
        out[O_NS + b] = (float)ns;
    }
}

extern "C" void kernel_launch(void* const* d_in, const int* in_sizes, int n_in,
                              void* d_out, int out_size) {
    const float* tokens        = (const float*)d_in[0];
    // d_in[1] = tokens_mask (bool) — unused; recomputed from num_tokens.
    const float* token_keys    = (const float*)d_in[2];
    const int*   num_tokens    = (const int*)  d_in[3];
    const float* query         = (const float*)d_in[4];
    const float* alignment     = (const float*)d_in[5];
    const float* cum_alignment = (const float*)d_in[6];
    const int*   window_start  = (const int*)  d_in[7];
    const float* conv_w        = (const float*)d_in[8];
    const float* conv_b        = (const float*)d_in[9];
    float* out = (float*)d_out;

    attn_cluster_kernel<<<2*BB, TPB>>>(tokens, token_keys, num_tokens, query,
                                       alignment, cum_alignment, window_start,
                                       conv_w, conv_b, out);
}